// round 11
// baseline (speedup 1.0000x reference)
#include <cuda_runtime.h>
#include <cuda_fp16.h>
#include <cstdint>
#include <cstddef>

#define NMAX 50000
#define DIN 96
#define DOUT 256

// ---------------- scratch (__device__ globals; no allocs allowed) ----------
__device__ float  g_agg[(size_t)NMAX * DIN];
__device__ __half g_x16[(size_t)NMAX * DIN];        // fp16 copy of x (gather source)
__device__ __half g_a16[(size_t)NMAX * DIN];        // fp16 agg [N][96]
__device__ __half g_h16[(size_t)NMAX * DOUT];       // fp16 h   [N][256]
__device__ __half g_b0ext[DOUT * (2 * DIN)];        // [256][192] = [W0h|W0l] (transposed)
__device__ __half g_b1t[DOUT * DOUT];               // [256][256] = W1^T (single fp16)

// ---------------- helpers ---------------------------------------------------
__device__ __forceinline__ uint32_t smem_u32(const void* p) {
    uint32_t a;
    asm("{ .reg .u64 t; cvta.to.shared.u64 t, %1; cvt.u32.u64 %0, t; }"
        : "=r"(a) : "l"(p));
    return a;
}
__device__ __forceinline__ void ldsm4(uint32_t* r, uint32_t addr) {
    asm volatile("ldmatrix.sync.aligned.m8n8.x4.shared.b16 {%0,%1,%2,%3}, [%4];"
                 : "=r"(r[0]), "=r"(r[1]), "=r"(r[2]), "=r"(r[3]) : "r"(addr));
}
__device__ __forceinline__ void mma16816(float* c, const uint32_t* a, const uint32_t* b) {
    asm volatile(
        "mma.sync.aligned.m16n8k16.row.col.f32.f16.f16.f32 "
        "{%0,%1,%2,%3}, {%4,%5,%6,%7}, {%8,%9}, {%0,%1,%2,%3};"
        : "+f"(c[0]), "+f"(c[1]), "+f"(c[2]), "+f"(c[3])
        : "r"(a[0]), "r"(a[1]), "r"(a[2]), "r"(a[3]), "r"(b[0]), "r"(b[1]));
}

// ---------------------------------------------------------------------------
// x fp32 -> fp16 copy (halves SpMM gather traffic)
// ---------------------------------------------------------------------------
__global__ void cvt_x_kernel(const float* __restrict__ x,
                             __half* __restrict__ x16, int n4) {
    int i = blockIdx.x * blockDim.x + threadIdx.x;
    if (i < n4) {
        float4 v = ((const float4*)x)[i];
        __half2 a = __floats2half2_rn(v.x, v.y);
        __half2 b = __floats2half2_rn(v.z, v.w);
        ((uint2*)x16)[i] = make_uint2(*(uint32_t*)&a, *(uint32_t*)&b);
    }
}

// ---------------------------------------------------------------------------
// agg = eps * x  (fp32 residual path, full precision)
// ---------------------------------------------------------------------------
__global__ void init_agg_kernel(const float* __restrict__ x,
                                const float* __restrict__ eps, int n4) {
    int i = blockIdx.x * blockDim.x + threadIdx.x;
    if (i < n4) {
        float e = eps[0];
        float4 v = ((const float4*)x)[i];
        v.x *= e; v.y *= e; v.z *= e; v.w *= e;
        ((float4*)g_agg)[i] = v;
    }
}

// ---------------------------------------------------------------------------
// agg[dst] += vals[e] * x16[src] via red.global.add.v4.f32
// 24 chunks/edge (same grid as the fp32 version): thread loads 4 halves (8B),
// issues one red.v4.f32.
// ---------------------------------------------------------------------------
__global__ void spmm_kernel(const __half* __restrict__ x16,
                            const int* __restrict__ src,
                            const int* __restrict__ dst,
                            const float* __restrict__ vals, int total) {
    int idx = blockIdx.x * blockDim.x + threadIdx.x;
    if (idx >= total) return;
    int e = idx / 24;
    int c = idx - e * 24;
    int s = src[e];
    int d = dst[e];
    float v = vals[e];
    uint2 pk = *(const uint2*)(x16 + (size_t)s * DIN + c * 4);
    float2 f0 = __half22float2(*(__half2*)&pk.x);
    float2 f1 = __half22float2(*(__half2*)&pk.y);
    float* p = g_agg + (size_t)d * DIN + c * 4;
    asm volatile("red.global.add.v4.f32 [%0], {%1,%2,%3,%4};"
                 :: "l"(p), "f"(v * f0.x), "f"(v * f0.y),
                    "f"(v * f1.x), "f"(v * f1.y) : "memory");
}

// ---------------------------------------------------------------------------
// agg fp32 -> fp16 (elementwise, vectorized)
// ---------------------------------------------------------------------------
__global__ void cvt_agg_kernel(const float* __restrict__ src,
                               __half* __restrict__ dstp, int n4) {
    int i = blockIdx.x * blockDim.x + threadIdx.x;
    if (i < n4) {
        float4 v = ((const float4*)src)[i];
        __half2 a = __floats2half2_rn(v.x, v.y);
        __half2 b = __floats2half2_rn(v.z, v.w);
        ((uint2*)dstp)[i] = make_uint2(*(uint32_t*)&a, *(uint32_t*)&b);
    }
}

// ---------------------------------------------------------------------------
// W0 fp32 [96][256] -> B0 fp16 [256][192] = [W0h|W0l] transposed (split)
// W1 fp32 [256][256] -> B1 fp16 [256][256] transposed (single)
// ---------------------------------------------------------------------------
__global__ void wprep_kernel(const float* __restrict__ W0,
                             const float* __restrict__ W1,
                             __half* __restrict__ B0,
                             __half* __restrict__ B1) {
    int i = blockIdx.x * blockDim.x + threadIdx.x;
    const int n0 = DIN * DOUT;
    if (i < n0) {
        int k = i / DOUT, n = i - k * DOUT;
        float v = W0[i];
        __half h = __float2half_rn(v);
        size_t base = (size_t)n * (2 * DIN);
        B0[base + k] = h;
        B0[base + DIN + k] = __float2half_rn(v - __half2float(h));
    } else if (i < n0 + DOUT * DOUT) {
        int j = i - n0;
        int k = j / DOUT, n = j - k * DOUT;
        B1[(size_t)n * DOUT + k] = __float2half_rn(W1[j]);
    }
}

// ---------------------------------------------------------------------------
// fp16 HMMA GEMM, 3-stage cp.async pipeline, optional K-wrap for A.
// ---------------------------------------------------------------------------
#define STG_BYTES (128 * 80)
#define NSTAGE 3
#define OFF_B (NSTAGE * STG_BYTES)
#define OFF_SC (2 * NSTAGE * STG_BYTES)
#define OFF_BI (OFF_SC + 512)
#define GEMM_SMEM (OFF_BI + 512)

template <int MODE, int KP, int WRAP>
__global__ void __launch_bounds__(256)
gemm_mma(const __half* __restrict__ Aext,
         const __half* __restrict__ Bext,
         float* __restrict__ Cf, __half* __restrict__ Ch, int M,
         const float* __restrict__ gamma, const float* __restrict__ beta,
         const float* __restrict__ mean, const float* __restrict__ var) {
    extern __shared__ __align__(16) unsigned char smem[];

    const int tid = threadIdx.x;
    const int wid = tid >> 5, lane = tid & 31;
    const int mBlock = blockIdx.y * 128, nBlock = blockIdx.x * 128;
    const int wm = wid & 3, wn = wid >> 2;
    const int tq = lane >> 2, tr = lane & 3;

    const uint32_t aBase = smem_u32(smem);
    const uint32_t bBase = aBase + OFF_B;
    float* s_sc = (float*)(smem + OFF_SC);
    float* s_bi = (float*)(smem + OFF_BI);

    const int ldrow = tid >> 2;
    const int ldkc = tid & 3;

    const int arow = ((lane >> 3) & 1) * 8 + (lane & 7);
    const int akb = (lane >> 4) * 8;
    const int brow = ((lane >> 4) & 1) * 8 + (lane & 7);
    const int bkb = ((lane >> 3) & 1) * 8;
    const uint32_t aAddr0 = aBase + (uint32_t)(wm * 32 + arow) * 80 + akb * 2;
    const uint32_t bAddr0 = bBase + (uint32_t)(wn * 64 + brow) * 80 + bkb * 2;

    float acc[2][8][4];
#pragma unroll
    for (int i = 0; i < 2; i++)
#pragma unroll
        for (int j = 0; j < 8; j++)
#pragma unroll
            for (int q = 0; q < 4; q++) acc[i][j][q] = 0.f;

    constexpr int NS = KP / 32;

    auto issue = [&](int ks, int stage) {
        const int k0 = ks * 32;
        const int ksA = (k0 >= WRAP) ? k0 - WRAP : k0;
#pragma unroll
        for (int i = 0; i < 2; i++) {
            int row = ldrow + i * 64;
            uint32_t sa = aBase + stage * STG_BYTES + row * 80 + ldkc * 16;
            const void* ga = Aext + (size_t)(mBlock + row) * WRAP + ksA + ldkc * 8;
            int sz = (mBlock + row < M) ? 16 : 0;
            asm volatile("cp.async.cg.shared.global [%0], [%1], 16, %2;"
                         :: "r"(sa), "l"(ga), "r"(sz) : "memory");
            uint32_t sb = bBase + stage * STG_BYTES + row * 80 + ldkc * 16;
            const void* gb = Bext + (size_t)(nBlock + row) * KP + k0 + ldkc * 8;
            asm volatile("cp.async.cg.shared.global [%0], [%1], 16;"
                         :: "r"(sb), "l"(gb) : "memory");
        }
        asm volatile("cp.async.commit_group;" ::: "memory");
    };

    issue(0, 0);
    if (NS > 1) issue(1, 1);

    for (int ks = 0; ks < NS; ks++) {
        if (ks + 1 < NS) {
            asm volatile("cp.async.wait_group 1;" ::: "memory");
        } else {
            asm volatile("cp.async.wait_group 0;" ::: "memory");
        }
        __syncthreads();
        if (ks + NSTAGE - 1 < NS)
            issue(ks + NSTAGE - 1, (ks + NSTAGE - 1) % NSTAGE);

        const int st = ks % NSTAGE;
        const uint32_t aS = aAddr0 + st * STG_BYTES;
        const uint32_t bS = bAddr0 + st * STG_BYTES;
#pragma unroll
        for (int ksub = 0; ksub < 2; ksub++) {
            uint32_t a[2][4];
#pragma unroll
            for (int mt = 0; mt < 2; mt++)
                ldsm4(a[mt], aS + mt * (16 * 80) + ksub * 32);
            uint32_t b[8][2];
#pragma unroll
            for (int np = 0; np < 4; np++) {
                uint32_t t[4];
                ldsm4(t, bS + np * (16 * 80) + ksub * 32);
                b[2 * np][0] = t[0]; b[2 * np][1] = t[1];
                b[2 * np + 1][0] = t[2]; b[2 * np + 1][1] = t[3];
            }
#pragma unroll
            for (int mt = 0; mt < 2; mt++)
#pragma unroll
                for (int nt = 0; nt < 8; nt++)
                    mma16816(acc[mt][nt], a[mt], b[nt]);
        }
    }
    __syncthreads();

    if (MODE == 0) {
        if (tid < 128) {
            int col = nBlock + tid;
            float s = gamma[col] * rsqrtf(var[col] + 1e-3f);
            s_sc[tid] = s;
            s_bi[tid] = beta[col] - mean[col] * s;
        }
        __syncthreads();
    }

#pragma unroll
    for (int mt = 0; mt < 2; mt++) {
        const int m0 = mBlock + wm * 32 + mt * 16 + tq;
#pragma unroll
        for (int nt = 0; nt < 8; nt++) {
            const int cloc = wn * 64 + nt * 8 + 2 * tr;
            const int col = nBlock + cloc;
            float* c = acc[mt][nt];
            if (MODE == 0) {
                float s0 = s_sc[cloc], s1 = s_sc[cloc + 1];
                float b0 = s_bi[cloc], b1 = s_bi[cloc + 1];
                if (m0 < M) {
                    float v0 = fmaxf(fmaf(c[0], s0, b0), 0.f);
                    float v1 = fmaxf(fmaf(c[1], s1, b1), 0.f);
                    __half2 p = __floats2half2_rn(v0, v1);
                    *(__half2*)(Ch + (size_t)m0 * DOUT + col) = p;
                }
                if (m0 + 8 < M) {
                    float v0 = fmaxf(fmaf(c[2], s0, b0), 0.f);
                    float v1 = fmaxf(fmaf(c[3], s1, b1), 0.f);
                    __half2 p = __floats2half2_rn(v0, v1);
                    *(__half2*)(Ch + (size_t)(m0 + 8) * DOUT + col) = p;
                }
            } else {
                if (m0 < M)
                    *(float2*)(Cf + (size_t)m0 * DOUT + col) =
                        make_float2(c[0], c[1]);
                if (m0 + 8 < M)
                    *(float2*)(Cf + (size_t)(m0 + 8) * DOUT + col) =
                        make_float2(c[2], c[3]);
            }
        }
    }
}

// ---------------------------------------------------------------------------
extern "C" void kernel_launch(void* const* d_in, const int* in_sizes, int n_in,
                              void* d_out, int out_size) {
    const float* x     = (const float*)d_in[0];
    const int*   src   = (const int*)d_in[1];
    const int*   dst   = (const int*)d_in[2];
    const float* vals  = (const float*)d_in[3];
    const float* eps   = (const float*)d_in[4];
    const float* W0    = (const float*)d_in[5];
    const float* W1    = (const float*)d_in[6];
    const float* gamma = (const float*)d_in[7];
    const float* beta  = (const float*)d_in[8];
    const float* mean  = (const float*)d_in[9];
    const float* var   = (const float*)d_in[10];

    int N = in_sizes[0] / DIN;
    int E = in_sizes[1];

    float* agg;            cudaGetSymbolAddress((void**)&agg, g_agg);
    __half *x16, *a16, *h16, *b0ext, *b1t;
    cudaGetSymbolAddress((void**)&x16, g_x16);
    cudaGetSymbolAddress((void**)&a16, g_a16);
    cudaGetSymbolAddress((void**)&h16, g_h16);
    cudaGetSymbolAddress((void**)&b0ext, g_b0ext);
    cudaGetSymbolAddress((void**)&b1t, g_b1t);

    cudaFuncSetAttribute(gemm_mma<0, 2 * DIN, DIN>,
                         cudaFuncAttributeMaxDynamicSharedMemorySize, GEMM_SMEM);
    cudaFuncSetAttribute(gemm_mma<1, DOUT, DOUT>,
                         cudaFuncAttributeMaxDynamicSharedMemorySize, GEMM_SMEM);

    // weight prep: W0 split, W1 plain transpose
    int wtot = DIN * DOUT + DOUT * DOUT;
    wprep_kernel<<<(wtot + 255) / 256, 256>>>(W0, W1, b0ext, b1t);

    int n4 = N * (DIN / 4);
    // 0. x -> fp16 gather copy
    cvt_x_kernel<<<(n4 + 255) / 256, 256>>>(x, x16, n4);

    // 1. agg = eps * x  (fp32)
    init_agg_kernel<<<(n4 + 255) / 256, 256>>>(x, eps, n4);

    // 2. scatter-add edge messages (fp16 gather, fp32 atomics, full grid)
    int total = E * (DIN / 4);
    spmm_kernel<<<(total + 255) / 256, 256>>>(x16, src, dst, vals, total);

    // 3. agg -> fp16
    cvt_agg_kernel<<<(n4 + 255) / 256, 256>>>(agg, a16, n4);

    // 4. h = relu(bn(agg @ W0))   (K' = 192, wrap 96: W0 hi/lo split)
    dim3 grid(DOUT / 128, (N + 127) / 128);
    gemm_mma<0, 2 * DIN, DIN><<<grid, 256, GEMM_SMEM>>>(
        a16, b0ext, nullptr, h16, N, gamma, beta, mean, var);

    // 5. out = h @ W1             (K = 256, no split)
    gemm_mma<1, DOUT, DOUT><<<grid, 256, GEMM_SMEM>>>(
        h16, b1t, (float*)d_out, nullptr, N,
        nullptr, nullptr, nullptr, nullptr);
}

// round 12
// speedup vs baseline: 1.1510x; 1.1510x over previous
#include <cuda_runtime.h>
#include <cuda_fp16.h>
#include <cstdint>
#include <cstddef>

#define NMAX 50000
#define DIN 96
#define DOUT 256

// ---------------- scratch (__device__ globals; no allocs allowed) ----------
__device__ float  g_agg[(size_t)NMAX * DIN];
__device__ __half g_a16[(size_t)NMAX * DIN];        // fp16 agg [N][96]
__device__ __half g_h16[(size_t)NMAX * DOUT];       // fp16 h   [N][256]
__device__ __half g_b0t[DOUT * DIN];                // [256][96]  = W0^T fp16
__device__ __half g_b1t[DOUT * DOUT];               // [256][256] = W1^T fp16

// ---------------- helpers ---------------------------------------------------
__device__ __forceinline__ uint32_t smem_u32(const void* p) {
    uint32_t a;
    asm("{ .reg .u64 t; cvta.to.shared.u64 t, %1; cvt.u32.u64 %0, t; }"
        : "=r"(a) : "l"(p));
    return a;
}
__device__ __forceinline__ void ldsm4(uint32_t* r, uint32_t addr) {
    asm volatile("ldmatrix.sync.aligned.m8n8.x4.shared.b16 {%0,%1,%2,%3}, [%4];"
                 : "=r"(r[0]), "=r"(r[1]), "=r"(r[2]), "=r"(r[3]) : "r"(addr));
}
__device__ __forceinline__ void mma16816(float* c, const uint32_t* a, const uint32_t* b) {
    asm volatile(
        "mma.sync.aligned.m16n8k16.row.col.f32.f16.f16.f32 "
        "{%0,%1,%2,%3}, {%4,%5,%6,%7}, {%8,%9}, {%0,%1,%2,%3};"
        : "+f"(c[0]), "+f"(c[1]), "+f"(c[2]), "+f"(c[3])
        : "r"(a[0]), "r"(a[1]), "r"(a[2]), "r"(a[3]), "r"(b[0]), "r"(b[1]));
}

// ---------------------------------------------------------------------------
// agg = eps * x  (fp32 residual path, full precision)
// ---------------------------------------------------------------------------
__global__ void init_agg_kernel(const float* __restrict__ x,
                                const float* __restrict__ eps, int n4) {
    int i = blockIdx.x * blockDim.x + threadIdx.x;
    if (i < n4) {
        float e = eps[0];
        float4 v = ((const float4*)x)[i];
        v.x *= e; v.y *= e; v.z *= e; v.w *= e;
        ((float4*)g_agg)[i] = v;
    }
}

// ---------------------------------------------------------------------------
// agg[dst] += vals[e] * x[src] via red.global.add.v4.f32  (fp32 gather)
// ---------------------------------------------------------------------------
__global__ void spmm_kernel(const float* __restrict__ x,
                            const int* __restrict__ src,
                            const int* __restrict__ dst,
                            const float* __restrict__ vals, int total) {
    int idx = blockIdx.x * blockDim.x + threadIdx.x;
    if (idx >= total) return;
    int e = idx / 24;
    int c = idx - e * 24;
    int s = src[e];
    int d = dst[e];
    float v = vals[e];
    float4 xv = *(const float4*)(x + (size_t)s * DIN + c * 4);
    float* p = g_agg + (size_t)d * DIN + c * 4;
    asm volatile("red.global.add.v4.f32 [%0], {%1,%2,%3,%4};"
                 :: "l"(p), "f"(v * xv.x), "f"(v * xv.y),
                    "f"(v * xv.z), "f"(v * xv.w) : "memory");
}

// ---------------------------------------------------------------------------
// agg fp32 -> fp16 (elementwise, vectorized)
// ---------------------------------------------------------------------------
__global__ void cvt_agg_kernel(const float* __restrict__ src,
                               __half* __restrict__ dstp, int n4) {
    int i = blockIdx.x * blockDim.x + threadIdx.x;
    if (i < n4) {
        float4 v = ((const float4*)src)[i];
        __half2 a = __floats2half2_rn(v.x, v.y);
        __half2 b = __floats2half2_rn(v.z, v.w);
        ((uint2*)dstp)[i] = make_uint2(*(uint32_t*)&a, *(uint32_t*)&b);
    }
}

// ---------------------------------------------------------------------------
// W0 fp32 [96][256]  -> B0 fp16 [256][96]  transposed
// W1 fp32 [256][256] -> B1 fp16 [256][256] transposed
// ---------------------------------------------------------------------------
__global__ void wprep_kernel(const float* __restrict__ W0,
                             const float* __restrict__ W1,
                             __half* __restrict__ B0,
                             __half* __restrict__ B1) {
    int i = blockIdx.x * blockDim.x + threadIdx.x;
    const int n0 = DIN * DOUT;
    if (i < n0) {
        int k = i / DOUT, n = i - k * DOUT;
        B0[(size_t)n * DIN + k] = __float2half_rn(W0[i]);
    } else if (i < n0 + DOUT * DOUT) {
        int j = i - n0;
        int k = j / DOUT, n = j - k * DOUT;
        B1[(size_t)n * DOUT + k] = __float2half_rn(W1[j]);
    }
}

// ---------------------------------------------------------------------------
// fp16 HMMA GEMM, 3-stage cp.async pipeline.
//   C[M,256] tile 128x128, 8 warps (4x2), warp tile 32x64, mma m16n8k16.
//   MODE 0: BN+ReLU epilogue, write fp16 Ch [M][256]
//   MODE 1: plain epilogue, write fp32 Cf [M][256]
// ---------------------------------------------------------------------------
#define STG_BYTES (128 * 80)
#define NSTAGE 3
#define OFF_B (NSTAGE * STG_BYTES)
#define OFF_SC (2 * NSTAGE * STG_BYTES)
#define OFF_BI (OFF_SC + 512)
#define GEMM_SMEM (OFF_BI + 512)

template <int MODE, int KP>
__global__ void __launch_bounds__(256)
gemm_mma(const __half* __restrict__ Aext,
         const __half* __restrict__ Bext,
         float* __restrict__ Cf, __half* __restrict__ Ch, int M,
         const float* __restrict__ gamma, const float* __restrict__ beta,
         const float* __restrict__ mean, const float* __restrict__ var) {
    extern __shared__ __align__(16) unsigned char smem[];

    const int tid = threadIdx.x;
    const int wid = tid >> 5, lane = tid & 31;
    const int mBlock = blockIdx.y * 128, nBlock = blockIdx.x * 128;
    const int wm = wid & 3, wn = wid >> 2;
    const int tq = lane >> 2, tr = lane & 3;

    const uint32_t aBase = smem_u32(smem);
    const uint32_t bBase = aBase + OFF_B;
    float* s_sc = (float*)(smem + OFF_SC);
    float* s_bi = (float*)(smem + OFF_BI);

    const int ldrow = tid >> 2;
    const int ldkc = tid & 3;

    const int arow = ((lane >> 3) & 1) * 8 + (lane & 7);
    const int akb = (lane >> 4) * 8;
    const int brow = ((lane >> 4) & 1) * 8 + (lane & 7);
    const int bkb = ((lane >> 3) & 1) * 8;
    const uint32_t aAddr0 = aBase + (uint32_t)(wm * 32 + arow) * 80 + akb * 2;
    const uint32_t bAddr0 = bBase + (uint32_t)(wn * 64 + brow) * 80 + bkb * 2;

    float acc[2][8][4];
#pragma unroll
    for (int i = 0; i < 2; i++)
#pragma unroll
        for (int j = 0; j < 8; j++)
#pragma unroll
            for (int q = 0; q < 4; q++) acc[i][j][q] = 0.f;

    constexpr int NS = KP / 32;

    auto issue = [&](int ks, int stage) {
        const int k0 = ks * 32;
#pragma unroll
        for (int i = 0; i < 2; i++) {
            int row = ldrow + i * 64;
            uint32_t sa = aBase + stage * STG_BYTES + row * 80 + ldkc * 16;
            const void* ga = Aext + (size_t)(mBlock + row) * KP + k0 + ldkc * 8;
            int sz = (mBlock + row < M) ? 16 : 0;
            asm volatile("cp.async.cg.shared.global [%0], [%1], 16, %2;"
                         :: "r"(sa), "l"(ga), "r"(sz) : "memory");
            uint32_t sb = bBase + stage * STG_BYTES + row * 80 + ldkc * 16;
            const void* gb = Bext + (size_t)(nBlock + row) * KP + k0 + ldkc * 8;
            asm volatile("cp.async.cg.shared.global [%0], [%1], 16;"
                         :: "r"(sb), "l"(gb) : "memory");
        }
        asm volatile("cp.async.commit_group;" ::: "memory");
    };

    issue(0, 0);
    if (NS > 1) issue(1, 1);

    for (int ks = 0; ks < NS; ks++) {
        if (ks + 1 < NS) {
            asm volatile("cp.async.wait_group 1;" ::: "memory");
        } else {
            asm volatile("cp.async.wait_group 0;" ::: "memory");
        }
        __syncthreads();
        if (ks + NSTAGE - 1 < NS)
            issue(ks + NSTAGE - 1, (ks + NSTAGE - 1) % NSTAGE);

        const int st = ks % NSTAGE;
        const uint32_t aS = aAddr0 + st * STG_BYTES;
        const uint32_t bS = bAddr0 + st * STG_BYTES;
#pragma unroll
        for (int ksub = 0; ksub < 2; ksub++) {
            uint32_t a[2][4];
#pragma unroll
            for (int mt = 0; mt < 2; mt++)
                ldsm4(a[mt], aS + mt * (16 * 80) + ksub * 32);
            uint32_t b[8][2];
#pragma unroll
            for (int np = 0; np < 4; np++) {
                uint32_t t[4];
                ldsm4(t, bS + np * (16 * 80) + ksub * 32);
                b[2 * np][0] = t[0]; b[2 * np][1] = t[1];
                b[2 * np + 1][0] = t[2]; b[2 * np + 1][1] = t[3];
            }
#pragma unroll
            for (int mt = 0; mt < 2; mt++)
#pragma unroll
                for (int nt = 0; nt < 8; nt++)
                    mma16816(acc[mt][nt], a[mt], b[nt]);
        }
    }
    __syncthreads();

    if (MODE == 0) {
        if (tid < 128) {
            int col = nBlock + tid;
            float s = gamma[col] * rsqrtf(var[col] + 1e-3f);
            s_sc[tid] = s;
            s_bi[tid] = beta[col] - mean[col] * s;
        }
        __syncthreads();
    }

#pragma unroll
    for (int mt = 0; mt < 2; mt++) {
        const int m0 = mBlock + wm * 32 + mt * 16 + tq;
#pragma unroll
        for (int nt = 0; nt < 8; nt++) {
            const int cloc = wn * 64 + nt * 8 + 2 * tr;
            const int col = nBlock + cloc;
            float* c = acc[mt][nt];
            if (MODE == 0) {
                float s0 = s_sc[cloc], s1 = s_sc[cloc + 1];
                float b0 = s_bi[cloc], b1 = s_bi[cloc + 1];
                if (m0 < M) {
                    float v0 = fmaxf(fmaf(c[0], s0, b0), 0.f);
                    float v1 = fmaxf(fmaf(c[1], s1, b1), 0.f);
                    __half2 p = __floats2half2_rn(v0, v1);
                    *(__half2*)(Ch + (size_t)m0 * DOUT + col) = p;
                }
                if (m0 + 8 < M) {
                    float v0 = fmaxf(fmaf(c[2], s0, b0), 0.f);
                    float v1 = fmaxf(fmaf(c[3], s1, b1), 0.f);
                    __half2 p = __floats2half2_rn(v0, v1);
                    *(__half2*)(Ch + (size_t)(m0 + 8) * DOUT + col) = p;
                }
            } else {
                if (m0 < M)
                    *(float2*)(Cf + (size_t)m0 * DOUT + col) =
                        make_float2(c[0], c[1]);
                if (m0 + 8 < M)
                    *(float2*)(Cf + (size_t)(m0 + 8) * DOUT + col) =
                        make_float2(c[2], c[3]);
            }
        }
    }
}

// ---------------------------------------------------------------------------
extern "C" void kernel_launch(void* const* d_in, const int* in_sizes, int n_in,
                              void* d_out, int out_size) {
    const float* x     = (const float*)d_in[0];
    const int*   src   = (const int*)d_in[1];
    const int*   dst   = (const int*)d_in[2];
    const float* vals  = (const float*)d_in[3];
    const float* eps   = (const float*)d_in[4];
    const float* W0    = (const float*)d_in[5];
    const float* W1    = (const float*)d_in[6];
    const float* gamma = (const float*)d_in[7];
    const float* beta  = (const float*)d_in[8];
    const float* mean  = (const float*)d_in[9];
    const float* var   = (const float*)d_in[10];

    int N = in_sizes[0] / DIN;
    int E = in_sizes[1];

    float* agg;            cudaGetSymbolAddress((void**)&agg, g_agg);
    __half *a16, *h16, *b0t, *b1t;
    cudaGetSymbolAddress((void**)&a16, g_a16);
    cudaGetSymbolAddress((void**)&h16, g_h16);
    cudaGetSymbolAddress((void**)&b0t, g_b0t);
    cudaGetSymbolAddress((void**)&b1t, g_b1t);

    cudaFuncSetAttribute(gemm_mma<0, DIN>,
                         cudaFuncAttributeMaxDynamicSharedMemorySize, GEMM_SMEM);
    cudaFuncSetAttribute(gemm_mma<1, DOUT>,
                         cudaFuncAttributeMaxDynamicSharedMemorySize, GEMM_SMEM);

    // weight prep: plain fp16 transposes
    int wtot = DIN * DOUT + DOUT * DOUT;
    wprep_kernel<<<(wtot + 255) / 256, 256>>>(W0, W1, b0t, b1t);

    int n4 = N * (DIN / 4);
    // 1. agg = eps * x  (fp32)
    init_agg_kernel<<<(n4 + 255) / 256, 256>>>(x, eps, n4);

    // 2. scatter-add edge messages (fp32 gather + fp32 v4 atomics)
    int total = E * (DIN / 4);
    spmm_kernel<<<(total + 255) / 256, 256>>>(x, src, dst, vals, total);

    // 3. agg -> fp16
    cvt_agg_kernel<<<(n4 + 255) / 256, 256>>>(agg, a16, n4);

    // 4. h = relu(bn(agg @ W0))   (K = 96, no split)
    dim3 grid(DOUT / 128, (N + 127) / 128);
    gemm_mma<0, DIN><<<grid, 256, GEMM_SMEM>>>(
        a16, b0t, nullptr, h16, N, gamma, beta, mean, var);

    // 5. out = h @ W1             (K = 256, no split)
    gemm_mma<1, DOUT><<<grid, 256, GEMM_SMEM>>>(
        h16, b1t, (float*)d_out, nullptr, N,
        nullptr, nullptr, nullptr, nullptr);
}

// round 13
// speedup vs baseline: 1.1574x; 1.0055x over previous
#include <cuda_runtime.h>
#include <cuda_fp16.h>
#include <cstdint>
#include <cstddef>

#define NMAX 50000
#define DIN 96
#define DOUT 256

// ---------------- scratch (__device__ globals; no allocs allowed) ----------
__device__ float  g_agg[(size_t)NMAX * DIN];
__device__ __half g_h16[(size_t)NMAX * DOUT];       // fp16 h   [N][256]
__device__ __half g_b0t[DOUT * DIN];                // [256][96]  = W0^T fp16
__device__ __half g_b1t[DOUT * DOUT];               // [256][256] = W1^T fp16

// ---------------- helpers ---------------------------------------------------
__device__ __forceinline__ uint32_t smem_u32(const void* p) {
    uint32_t a;
    asm("{ .reg .u64 t; cvta.to.shared.u64 t, %1; cvt.u32.u64 %0, t; }"
        : "=r"(a) : "l"(p));
    return a;
}
__device__ __forceinline__ void ldsm4(uint32_t* r, uint32_t addr) {
    asm volatile("ldmatrix.sync.aligned.m8n8.x4.shared.b16 {%0,%1,%2,%3}, [%4];"
                 : "=r"(r[0]), "=r"(r[1]), "=r"(r[2]), "=r"(r[3]) : "r"(addr));
}
__device__ __forceinline__ void mma16816(float* c, const uint32_t* a, const uint32_t* b) {
    asm volatile(
        "mma.sync.aligned.m16n8k16.row.col.f32.f16.f16.f32 "
        "{%0,%1,%2,%3}, {%4,%5,%6,%7}, {%8,%9}, {%0,%1,%2,%3};"
        : "+f"(c[0]), "+f"(c[1]), "+f"(c[2]), "+f"(c[3])
        : "r"(a[0]), "r"(a[1]), "r"(a[2]), "r"(a[3]), "r"(b[0]), "r"(b[1]));
}

// ---------------------------------------------------------------------------
// Combined prologue: agg = eps*x  AND  weight fp16 transposes
// ---------------------------------------------------------------------------
__global__ void prep_kernel(const float* __restrict__ x,
                            const float* __restrict__ eps,
                            const float* __restrict__ W0,
                            const float* __restrict__ W1,
                            __half* __restrict__ B0,
                            __half* __restrict__ B1, int n4) {
    int i = blockIdx.x * blockDim.x + threadIdx.x;
    if (i < n4) {
        float e = eps[0];
        float4 v = ((const float4*)x)[i];
        v.x *= e; v.y *= e; v.z *= e; v.w *= e;
        ((float4*)g_agg)[i] = v;
        return;
    }
    int j = i - n4;
    const int n0 = DIN * DOUT;
    if (j < n0) {
        int k = j / DOUT, n = j - k * DOUT;
        B0[(size_t)n * DIN + k] = __float2half_rn(W0[j]);
    } else if (j < n0 + DOUT * DOUT) {
        int q = j - n0;
        int k = q / DOUT, n = q - k * DOUT;
        B1[(size_t)n * DOUT + k] = __float2half_rn(W1[q]);
    }
}

// ---------------------------------------------------------------------------
// agg[dst] += vals[e] * x[src] via red.global.add.v4.f32  (fp32 gather)
// ---------------------------------------------------------------------------
__global__ void spmm_kernel(const float* __restrict__ x,
                            const int* __restrict__ src,
                            const int* __restrict__ dst,
                            const float* __restrict__ vals, int total) {
    int idx = blockIdx.x * blockDim.x + threadIdx.x;
    if (idx >= total) return;
    int e = idx / 24;
    int c = idx - e * 24;
    int s = src[e];
    int d = dst[e];
    float v = vals[e];
    float4 xv = *(const float4*)(x + (size_t)s * DIN + c * 4);
    float* p = g_agg + (size_t)d * DIN + c * 4;
    asm volatile("red.global.add.v4.f32 [%0], {%1,%2,%3,%4};"
                 :: "l"(p), "f"(v * xv.x), "f"(v * xv.y),
                    "f"(v * xv.z), "f"(v * xv.w) : "memory");
}

// ---------------------------------------------------------------------------
// GEMM0 fused: h16 = relu(bn(agg_fp32 @ W0)), converting A fp32->fp16 in-smem.
// Tile 128x128, 8 warps, K=96 (NS=3). 3-stage cp.async for fp32 A + fp16 B.
// ---------------------------------------------------------------------------
#define A32_STG 18432                       // 128 rows * 144B (128B data + pad)
#define F_OFF_A16 (3 * A32_STG)             // 55296, fp16 convert buffer 10240
#define F_OFF_B   (F_OFF_A16 + 10240)       // 65536, 3 stages * 10240
#define F_OFF_SC  (F_OFF_B + 3 * 10240)     // 96256
#define F_OFF_BI  (F_OFF_SC + 512)
#define F_SMEM    (F_OFF_BI + 512)          // 97280

__global__ void __launch_bounds__(256)
gemm0_fused(const float* __restrict__ A32,
            const __half* __restrict__ Bt,
            __half* __restrict__ Ch, int M,
            const float* __restrict__ gamma, const float* __restrict__ beta,
            const float* __restrict__ mean, const float* __restrict__ var) {
    extern __shared__ __align__(16) unsigned char smem[];

    const int tid = threadIdx.x;
    const int wid = tid >> 5, lane = tid & 31;
    const int mBlock = blockIdx.y * 128, nBlock = blockIdx.x * 128;
    const int wm = wid & 3, wn = wid >> 2;
    const int tq = lane >> 2, tr = lane & 3;

    const uint32_t sBase = smem_u32(smem);
    float* s_sc = (float*)(smem + F_OFF_SC);
    float* s_bi = (float*)(smem + F_OFF_BI);

    // loaders
    const int aRow = tid >> 1, aHalf = tid & 1;       // A32: 128 rows x 128B
    const int ldrow = tid >> 2, ldkc = tid & 3;       // B: 128 rows x 64B

    // ldmatrix lane offsets
    const int arow = ((lane >> 3) & 1) * 8 + (lane & 7);
    const int akb = (lane >> 4) * 8;
    const int brow = ((lane >> 4) & 1) * 8 + (lane & 7);
    const int bkb = ((lane >> 3) & 1) * 8;
    const uint32_t aAddr0 = sBase + F_OFF_A16 + (uint32_t)(wm * 32 + arow) * 80 + akb * 2;
    const uint32_t bAddr0 = sBase + F_OFF_B + (uint32_t)(wn * 64 + brow) * 80 + bkb * 2;

    float acc[2][8][4];
#pragma unroll
    for (int i = 0; i < 2; i++)
#pragma unroll
        for (int j = 0; j < 8; j++)
#pragma unroll
            for (int q = 0; q < 4; q++) acc[i][j][q] = 0.f;

    const int NS = 3;   // K = 96 = 3 * 32

    auto issue = [&](int ks, int stage) {
        const int k0 = ks * 32;
        // A fp32: thread covers 64B of its row
        {
            uint32_t sa = sBase + stage * A32_STG + aRow * 144 + aHalf * 64;
            const float* ga = A32 + (size_t)(mBlock + aRow) * DIN + k0 + aHalf * 16;
            int sz = (mBlock + aRow < M) ? 16 : 0;
#pragma unroll
            for (int j = 0; j < 4; j++)
                asm volatile("cp.async.cg.shared.global [%0], [%1], 16, %2;"
                             :: "r"(sa + j * 16), "l"(ga + j * 4), "r"(sz) : "memory");
        }
        // B fp16
#pragma unroll
        for (int i = 0; i < 2; i++) {
            int row = ldrow + i * 64;
            uint32_t sb = sBase + F_OFF_B + stage * 10240 + row * 80 + ldkc * 16;
            const void* gb = Bt + (size_t)(nBlock + row) * DIN + k0 + ldkc * 8;
            asm volatile("cp.async.cg.shared.global [%0], [%1], 16;"
                         :: "r"(sb), "l"(gb) : "memory");
        }
        asm volatile("cp.async.commit_group;" ::: "memory");
    };

    issue(0, 0);
    issue(1, 1);

    for (int ks = 0; ks < NS; ks++) {
        if (ks + 1 < NS) {
            asm volatile("cp.async.wait_group 1;" ::: "memory");
        } else {
            asm volatile("cp.async.wait_group 0;" ::: "memory");
        }
        __syncthreads();   // stage ks resident; A16 buffer free (prev mma done)

        const int st = ks % 3;
        // convert A32[st] -> A16 (fp16). 4096 elems, 16 per thread.
        {
            const float* srcf = (const float*)(smem + st * A32_STG + aRow * 144 + aHalf * 64);
            __half* d16 = (__half*)(smem + F_OFF_A16 + aRow * 80 + aHalf * 32);
            uint32_t buf[8];
#pragma unroll
            for (int j = 0; j < 4; j++) {
                float4 v = ((const float4*)srcf)[j];
                __half2 p0 = __floats2half2_rn(v.x, v.y);
                __half2 p1 = __floats2half2_rn(v.z, v.w);
                buf[2 * j] = *(uint32_t*)&p0;
                buf[2 * j + 1] = *(uint32_t*)&p1;
            }
            ((uint4*)d16)[0] = ((uint4*)buf)[0];
            ((uint4*)d16)[1] = ((uint4*)buf)[1];
        }
        if (ks + 2 < NS) issue(ks + 2, (ks + 2) % 3);
        __syncthreads();   // A16 ready

#pragma unroll
        for (int ksub = 0; ksub < 2; ksub++) {
            uint32_t a[2][4];
#pragma unroll
            for (int mt = 0; mt < 2; mt++)
                ldsm4(a[mt], aAddr0 + mt * (16 * 80) + ksub * 32);
            uint32_t b[8][2];
#pragma unroll
            for (int np = 0; np < 4; np++) {
                uint32_t t[4];
                ldsm4(t, bAddr0 + st * 10240 + np * (16 * 80) + ksub * 32);
                b[2 * np][0] = t[0]; b[2 * np][1] = t[1];
                b[2 * np + 1][0] = t[2]; b[2 * np + 1][1] = t[3];
            }
#pragma unroll
            for (int mt = 0; mt < 2; mt++)
#pragma unroll
                for (int nt = 0; nt < 8; nt++)
                    mma16816(acc[mt][nt], a[mt], b[nt]);
        }
    }
    __syncthreads();

    if (tid < 128) {
        int col = nBlock + tid;
        float s = gamma[col] * rsqrtf(var[col] + 1e-3f);
        s_sc[tid] = s;
        s_bi[tid] = beta[col] - mean[col] * s;
    }
    __syncthreads();

#pragma unroll
    for (int mt = 0; mt < 2; mt++) {
        const int m0 = mBlock + wm * 32 + mt * 16 + tq;
#pragma unroll
        for (int nt = 0; nt < 8; nt++) {
            const int cloc = wn * 64 + nt * 8 + 2 * tr;
            const int col = nBlock + cloc;
            float* c = acc[mt][nt];
            float s0 = s_sc[cloc], s1 = s_sc[cloc + 1];
            float b0 = s_bi[cloc], b1 = s_bi[cloc + 1];
            if (m0 < M) {
                float v0 = fmaxf(fmaf(c[0], s0, b0), 0.f);
                float v1 = fmaxf(fmaf(c[1], s1, b1), 0.f);
                __half2 p = __floats2half2_rn(v0, v1);
                *(__half2*)(Ch + (size_t)m0 * DOUT + col) = p;
            }
            if (m0 + 8 < M) {
                float v0 = fmaxf(fmaf(c[2], s0, b0), 0.f);
                float v1 = fmaxf(fmaf(c[3], s1, b1), 0.f);
                __half2 p = __floats2half2_rn(v0, v1);
                *(__half2*)(Ch + (size_t)(m0 + 8) * DOUT + col) = p;
            }
        }
    }
}

// ---------------------------------------------------------------------------
// GEMM1: fp16 HMMA GEMM (unchanged R12 pipeline), K=256, fp32 output.
// ---------------------------------------------------------------------------
#define STG_BYTES (128 * 80)
#define NSTAGE 3
#define OFF_B (NSTAGE * STG_BYTES)
#define GEMM_SMEM (2 * NSTAGE * STG_BYTES)

template <int KP>
__global__ void __launch_bounds__(256)
gemm_mma(const __half* __restrict__ Aext,
         const __half* __restrict__ Bext,
         float* __restrict__ Cf, int M) {
    extern __shared__ __align__(16) unsigned char smem[];

    const int tid = threadIdx.x;
    const int wid = tid >> 5, lane = tid & 31;
    const int mBlock = blockIdx.y * 128, nBlock = blockIdx.x * 128;
    const int wm = wid & 3, wn = wid >> 2;
    const int tq = lane >> 2, tr = lane & 3;

    const uint32_t aBase = smem_u32(smem);
    const uint32_t bBase = aBase + OFF_B;

    const int ldrow = tid >> 2;
    const int ldkc = tid & 3;

    const int arow = ((lane >> 3) & 1) * 8 + (lane & 7);
    const int akb = (lane >> 4) * 8;
    const int brow = ((lane >> 4) & 1) * 8 + (lane & 7);
    const int bkb = ((lane >> 3) & 1) * 8;
    const uint32_t aAddr0 = aBase + (uint32_t)(wm * 32 + arow) * 80 + akb * 2;
    const uint32_t bAddr0 = bBase + (uint32_t)(wn * 64 + brow) * 80 + bkb * 2;

    float acc[2][8][4];
#pragma unroll
    for (int i = 0; i < 2; i++)
#pragma unroll
        for (int j = 0; j < 8; j++)
#pragma unroll
            for (int q = 0; q < 4; q++) acc[i][j][q] = 0.f;

    constexpr int NS = KP / 32;

    auto issue = [&](int ks, int stage) {
        const int k0 = ks * 32;
#pragma unroll
        for (int i = 0; i < 2; i++) {
            int row = ldrow + i * 64;
            uint32_t sa = aBase + stage * STG_BYTES + row * 80 + ldkc * 16;
            const void* ga = Aext + (size_t)(mBlock + row) * KP + k0 + ldkc * 8;
            int sz = (mBlock + row < M) ? 16 : 0;
            asm volatile("cp.async.cg.shared.global [%0], [%1], 16, %2;"
                         :: "r"(sa), "l"(ga), "r"(sz) : "memory");
            uint32_t sb = bBase + stage * STG_BYTES + row * 80 + ldkc * 16;
            const void* gb = Bext + (size_t)(nBlock + row) * KP + k0 + ldkc * 8;
            asm volatile("cp.async.cg.shared.global [%0], [%1], 16;"
                         :: "r"(sb), "l"(gb) : "memory");
        }
        asm volatile("cp.async.commit_group;" ::: "memory");
    };

    issue(0, 0);
    if (NS > 1) issue(1, 1);

    for (int ks = 0; ks < NS; ks++) {
        if (ks + 1 < NS) {
            asm volatile("cp.async.wait_group 1;" ::: "memory");
        } else {
            asm volatile("cp.async.wait_group 0;" ::: "memory");
        }
        __syncthreads();
        if (ks + NSTAGE - 1 < NS)
            issue(ks + NSTAGE - 1, (ks + NSTAGE - 1) % NSTAGE);

        const int st = ks % NSTAGE;
        const uint32_t aS = aAddr0 + st * STG_BYTES;
        const uint32_t bS = bAddr0 + st * STG_BYTES;
#pragma unroll
        for (int ksub = 0; ksub < 2; ksub++) {
            uint32_t a[2][4];
#pragma unroll
            for (int mt = 0; mt < 2; mt++)
                ldsm4(a[mt], aS + mt * (16 * 80) + ksub * 32);
            uint32_t b[8][2];
#pragma unroll
            for (int np = 0; np < 4; np++) {
                uint32_t t[4];
                ldsm4(t, bS + np * (16 * 80) + ksub * 32);
                b[2 * np][0] = t[0]; b[2 * np][1] = t[1];
                b[2 * np + 1][0] = t[2]; b[2 * np + 1][1] = t[3];
            }
#pragma unroll
            for (int mt = 0; mt < 2; mt++)
#pragma unroll
                for (int nt = 0; nt < 8; nt++)
                    mma16816(acc[mt][nt], a[mt], b[nt]);
        }
    }
    __syncthreads();

#pragma unroll
    for (int mt = 0; mt < 2; mt++) {
        const int m0 = mBlock + wm * 32 + mt * 16 + tq;
#pragma unroll
        for (int nt = 0; nt < 8; nt++) {
            const int cloc = wn * 64 + nt * 8 + 2 * tr;
            const int col = nBlock + cloc;
            float* c = acc[mt][nt];
            if (m0 < M)
                *(float2*)(Cf + (size_t)m0 * DOUT + col) = make_float2(c[0], c[1]);
            if (m0 + 8 < M)
                *(float2*)(Cf + (size_t)(m0 + 8) * DOUT + col) = make_float2(c[2], c[3]);
        }
    }
}

// ---------------------------------------------------------------------------
extern "C" void kernel_launch(void* const* d_in, const int* in_sizes, int n_in,
                              void* d_out, int out_size) {
    const float* x     = (const float*)d_in[0];
    const int*   src   = (const int*)d_in[1];
    const int*   dst   = (const int*)d_in[2];
    const float* vals  = (const float*)d_in[3];
    const float* eps   = (const float*)d_in[4];
    const float* W0    = (const float*)d_in[5];
    const float* W1    = (const float*)d_in[6];
    const float* gamma = (const float*)d_in[7];
    const float* beta  = (const float*)d_in[8];
    const float* mean  = (const float*)d_in[9];
    const float* var   = (const float*)d_in[10];

    int N = in_sizes[0] / DIN;
    int E = in_sizes[1];

    float* agg;            cudaGetSymbolAddress((void**)&agg, g_agg);
    __half *h16, *b0t, *b1t;
    cudaGetSymbolAddress((void**)&h16, g_h16);
    cudaGetSymbolAddress((void**)&b0t, g_b0t);
    cudaGetSymbolAddress((void**)&b1t, g_b1t);

    cudaFuncSetAttribute(gemm0_fused,
                         cudaFuncAttributeMaxDynamicSharedMemorySize, F_SMEM);
    cudaFuncSetAttribute(gemm_mma<DOUT>,
                         cudaFuncAttributeMaxDynamicSharedMemorySize, GEMM_SMEM);

    int n4 = N * (DIN / 4);
    int wtot = DIN * DOUT + DOUT * DOUT;

    // 1. prologue: agg = eps*x  +  weight fp16 transposes (one launch)
    prep_kernel<<<(n4 + wtot + 255) / 256, 256>>>(x, eps, W0, W1, b0t, b1t, n4);

    // 2. scatter-add edge messages (fp32 gather + fp32 v4 atomics)
    int total = E * (DIN / 4);
    spmm_kernel<<<(total + 255) / 256, 256>>>(x, src, dst, vals, total);

    // 3. h = relu(bn(agg @ W0)), fp32 A converted in-kernel
    dim3 grid(DOUT / 128, (N + 127) / 128);
    gemm0_fused<<<grid, 256, F_SMEM>>>(agg, b0t, h16, N, gamma, beta, mean, var);

    // 4. out = h @ W1
    gemm_mma<DOUT><<<grid, 256, GEMM_SMEM>>>(h16, b1t, (float*)d_out, N);
}